// round 1
// baseline (speedup 1.0000x reference)
#include <cuda_runtime.h>
#include <cuda_bf16.h>

// Problem constants (GraphSAGENet): 50000 nodes, 800000 edges, 96 -> 48 -> 48 -> 48 -> 1
constexpr int NN = 50000;
constexpr int NE = 800000;
constexpr int F0 = 96;
constexpr int H  = 48;

// Scratch (static device globals; allocation at module load, not in kernel_launch)
__device__ float g_y  [NN * H];   // transformed neighbor features (h @ W_neigh)
__device__ float g_agg[NN * H];   // scatter-add accumulator
__device__ float g_h1 [NN * H];
__device__ float g_h2 [NN * H];
__device__ float g_h3 [NN * H];
__device__ int   g_deg [NN];
__device__ float g_dinv[NN];

// ---------------------------------------------------------------------------
// degree histogram
// ---------------------------------------------------------------------------
__global__ void k_zero_deg() {
    int i = blockIdx.x * blockDim.x + threadIdx.x;
    if (i < NN) g_deg[i] = 0;
}

__global__ void k_count_deg(const int* __restrict__ dst) {
    int e = blockIdx.x * blockDim.x + threadIdx.x;
    if (e < NE) atomicAdd(&g_deg[dst[e]], 1);
}

__global__ void k_dinv() {
    int i = blockIdx.x * blockDim.x + threadIdx.x;
    if (i < NN) {
        int d = g_deg[i];
        g_dinv[i] = 1.0f / (float)(d > 1 ? d : 1);
    }
}

// ---------------------------------------------------------------------------
// y = in @ W_neigh  (K x 48), and zero the agg buffer for the upcoming scatter
// One thread per node, W staged in shared, 48 accumulators in registers.
// ---------------------------------------------------------------------------
template <int K>
__global__ void k_neigh_gemm(const float* __restrict__ in,
                             const float* __restrict__ W,
                             float* __restrict__ y,
                             float* __restrict__ agg) {
    __shared__ float sw[K * H];
    for (int i = threadIdx.x; i < K * H; i += blockDim.x) sw[i] = W[i];
    __syncthreads();

    int node = blockIdx.x * blockDim.x + threadIdx.x;
    if (node >= NN) return;

    float acc[H];
#pragma unroll
    for (int j = 0; j < H; j++) acc[j] = 0.0f;

    const float4* row = reinterpret_cast<const float4*>(in + (size_t)node * K);
#pragma unroll 4
    for (int k0 = 0; k0 < K / 4; k0++) {
        float4 a = row[k0];
        const float av[4] = {a.x, a.y, a.z, a.w};
#pragma unroll
        for (int kk = 0; kk < 4; kk++) {
            float s = av[kk];
            const float* wr = &sw[(k0 * 4 + kk) * H];
#pragma unroll
            for (int j = 0; j < H; j++) acc[j] += s * wr[j];
        }
    }

    float4* yo = reinterpret_cast<float4*>(y + (size_t)node * H);
    float4* ao = reinterpret_cast<float4*>(agg + (size_t)node * H);
#pragma unroll
    for (int j4 = 0; j4 < H / 4; j4++) {
        float4 v;
        v.x = acc[j4 * 4 + 0]; v.y = acc[j4 * 4 + 1];
        v.z = acc[j4 * 4 + 2]; v.w = acc[j4 * 4 + 3];
        yo[j4] = v;
        ao[j4] = make_float4(0.f, 0.f, 0.f, 0.f);
    }
}

// ---------------------------------------------------------------------------
// scatter: agg[dst] += y[src]   (48 floats = 12x red.global.add.v4.f32)
// ---------------------------------------------------------------------------
__global__ void k_scatter(const int* __restrict__ src,
                          const int* __restrict__ dst,
                          const float* __restrict__ y,
                          float* __restrict__ agg) {
    int e = blockIdx.x * blockDim.x + threadIdx.x;
    if (e >= NE) return;
    int s = src[e];
    int d = dst[e];
    const float4* ys = reinterpret_cast<const float4*>(y + (size_t)s * H);
    float4* ad = reinterpret_cast<float4*>(agg + (size_t)d * H);
#pragma unroll
    for (int c = 0; c < H / 4; c++) {
        float4 v = ys[c];
        asm volatile("red.global.add.v4.f32 [%0], {%1, %2, %3, %4};"
                     :: "l"(ad + c), "f"(v.x), "f"(v.y), "f"(v.z), "f"(v.w)
                     : "memory");
    }
}

// ---------------------------------------------------------------------------
// out = relu(in @ W_self + b + agg * dinv)
// ---------------------------------------------------------------------------
template <int K>
__global__ void k_combine(const float* __restrict__ in,
                          const float* __restrict__ W,
                          const float* __restrict__ b,
                          const float* __restrict__ agg,
                          float* __restrict__ out) {
    __shared__ float sw[K * H];
    __shared__ float sb[H];
    for (int i = threadIdx.x; i < K * H; i += blockDim.x) sw[i] = W[i];
    if (threadIdx.x < H) sb[threadIdx.x] = b[threadIdx.x];
    __syncthreads();

    int node = blockIdx.x * blockDim.x + threadIdx.x;
    if (node >= NN) return;

    float acc[H];
#pragma unroll
    for (int j = 0; j < H; j++) acc[j] = 0.0f;

    const float4* row = reinterpret_cast<const float4*>(in + (size_t)node * K);
#pragma unroll 4
    for (int k0 = 0; k0 < K / 4; k0++) {
        float4 a = row[k0];
        const float av[4] = {a.x, a.y, a.z, a.w};
#pragma unroll
        for (int kk = 0; kk < 4; kk++) {
            float s = av[kk];
            const float* wr = &sw[(k0 * 4 + kk) * H];
#pragma unroll
            for (int j = 0; j < H; j++) acc[j] += s * wr[j];
        }
    }

    float di = g_dinv[node];
    const float4* ar = reinterpret_cast<const float4*>(agg + (size_t)node * H);
    float4* oo = reinterpret_cast<float4*>(out + (size_t)node * H);
#pragma unroll
    for (int j4 = 0; j4 < H / 4; j4++) {
        float4 a = ar[j4];
        float4 v;
        v.x = acc[j4 * 4 + 0] + sb[j4 * 4 + 0] + a.x * di;
        v.y = acc[j4 * 4 + 1] + sb[j4 * 4 + 1] + a.y * di;
        v.z = acc[j4 * 4 + 2] + sb[j4 * 4 + 2] + a.z * di;
        v.w = acc[j4 * 4 + 3] + sb[j4 * 4 + 3] + a.w * di;
        v.x = fmaxf(v.x, 0.f); v.y = fmaxf(v.y, 0.f);
        v.z = fmaxf(v.z, 0.f); v.w = fmaxf(v.w, 0.f);
        oo[j4] = v;
    }
}

// ---------------------------------------------------------------------------
// prediction head: out[n] = h[n,:] @ w_pred + b_pred
// ---------------------------------------------------------------------------
__global__ void k_pred(const float* __restrict__ h,
                       const float* __restrict__ wp,
                       const float* __restrict__ bp,
                       float* __restrict__ out) {
    __shared__ float sw[H];
    if (threadIdx.x < H) sw[threadIdx.x] = wp[threadIdx.x];
    __syncthreads();

    int node = blockIdx.x * blockDim.x + threadIdx.x;
    if (node >= NN) return;

    const float4* row = reinterpret_cast<const float4*>(h + (size_t)node * H);
    float acc = 0.0f;
#pragma unroll
    for (int j4 = 0; j4 < H / 4; j4++) {
        float4 a = row[j4];
        acc += a.x * sw[j4 * 4 + 0];
        acc += a.y * sw[j4 * 4 + 1];
        acc += a.z * sw[j4 * 4 + 2];
        acc += a.w * sw[j4 * 4 + 3];
    }
    out[node] = acc + bp[0];
}

// ---------------------------------------------------------------------------
extern "C" void kernel_launch(void* const* d_in, const int* in_sizes, int n_in,
                              void* d_out, int out_size) {
    const float* x        = (const float*)d_in[0];
    const int*   edge     = (const int*)d_in[1];
    const float* w_self0  = (const float*)d_in[2];
    const float* w_neigh0 = (const float*)d_in[3];
    const float* b0       = (const float*)d_in[4];
    const float* w_self1  = (const float*)d_in[5];
    const float* w_neigh1 = (const float*)d_in[6];
    const float* b1       = (const float*)d_in[7];
    const float* w_self2  = (const float*)d_in[8];
    const float* w_neigh2 = (const float*)d_in[9];
    const float* b2       = (const float*)d_in[10];
    const float* w_pred   = (const float*)d_in[11];
    const float* b_pred   = (const float*)d_in[12];
    float* out = (float*)d_out;

    const int* src = edge;
    const int* dst = edge + NE;

    float *y, *agg, *h1, *h2, *h3;
    cudaGetSymbolAddress((void**)&y,   g_y);
    cudaGetSymbolAddress((void**)&agg, g_agg);
    cudaGetSymbolAddress((void**)&h1,  g_h1);
    cudaGetSymbolAddress((void**)&h2,  g_h2);
    cudaGetSymbolAddress((void**)&h3,  g_h3);

    const int TB_N = 128;
    const int gN = (NN + TB_N - 1) / TB_N;
    const int gE = (NE + 255) / 256;

    // degree -> inverse degree
    k_zero_deg<<<(NN + 255) / 256, 256>>>();
    k_count_deg<<<gE, 256>>>(dst);
    k_dinv<<<(NN + 255) / 256, 256>>>();

    // Layer 0 (96 -> 48)
    k_neigh_gemm<F0><<<gN, TB_N>>>(x, w_neigh0, y, agg);
    k_scatter<<<gE, 256>>>(src, dst, y, agg);
    k_combine<F0><<<gN, TB_N>>>(x, w_self0, b0, agg, h1);

    // Layer 1 (48 -> 48)
    k_neigh_gemm<H><<<gN, TB_N>>>(h1, w_neigh1, y, agg);
    k_scatter<<<gE, 256>>>(src, dst, y, agg);
    k_combine<H><<<gN, TB_N>>>(h1, w_self1, b1, agg, h2);

    // Layer 2 (48 -> 48)
    k_neigh_gemm<H><<<gN, TB_N>>>(h2, w_neigh2, y, agg);
    k_scatter<<<gE, 256>>>(src, dst, y, agg);
    k_combine<H><<<gN, TB_N>>>(h2, w_self2, b2, agg, h3);

    // Prediction head
    k_pred<<<gN, TB_N>>>(h3, w_pred, b_pred, out);
}

// round 2
// speedup vs baseline: 1.4650x; 1.4650x over previous
#include <cuda_runtime.h>
#include <cuda_bf16.h>

// GraphSAGENet: 50000 nodes, 800000 edges, feats 96 -> 48 -> 48 -> 48 -> 1
constexpr int NN = 50000;
constexpr int NE = 800000;
constexpr int F0 = 96;
constexpr int H  = 48;

constexpr int SCAN_BLOCKS = (NN + 255) / 256;   // 196

// Scratch (static device globals)
__device__ float g_y0[NN * H];
__device__ float g_y1[NN * H];
__device__ float g_h0[NN * H];
__device__ float g_h1[NN * H];
__device__ int   g_deg[NN];
__device__ float g_dinv[NN];
__device__ int   g_rowptr[NN];
__device__ int   g_cursor[NN];
__device__ int   g_col[NE];
__device__ int   g_blksum[256];

// ---------------------------------------------------------------------------
// CSR build: histogram -> 2-level exclusive scan -> atomic-cursor fill
// ---------------------------------------------------------------------------
__global__ void k_zero_deg() {
    int i = blockIdx.x * blockDim.x + threadIdx.x;
    if (i < NN) g_deg[i] = 0;
}

__global__ void k_count_deg(const int* __restrict__ dst) {
    int e = blockIdx.x * blockDim.x + threadIdx.x;
    if (e < NE) atomicAdd(&g_deg[dst[e]], 1);
}

__global__ void k_scan1() {
    __shared__ int s[256];
    int i = blockIdx.x * 256 + threadIdx.x;
    int v = (i < NN) ? g_deg[i] : 0;
    s[threadIdx.x] = v;
    __syncthreads();
#pragma unroll
    for (int off = 1; off < 256; off <<= 1) {
        int t = (threadIdx.x >= off) ? s[threadIdx.x - off] : 0;
        __syncthreads();
        s[threadIdx.x] += t;
        __syncthreads();
    }
    if (i < NN) g_rowptr[i] = s[threadIdx.x] - v;      // local exclusive
    if (threadIdx.x == 255) g_blksum[blockIdx.x] = s[255];
}

__global__ void k_scan2() {
    __shared__ int s[256];
    int v = (threadIdx.x < SCAN_BLOCKS) ? g_blksum[threadIdx.x] : 0;
    s[threadIdx.x] = v;
    __syncthreads();
#pragma unroll
    for (int off = 1; off < 256; off <<= 1) {
        int t = (threadIdx.x >= off) ? s[threadIdx.x - off] : 0;
        __syncthreads();
        s[threadIdx.x] += t;
        __syncthreads();
    }
    g_blksum[threadIdx.x] = s[threadIdx.x] - v;        // exclusive
}

__global__ void k_scan3() {
    int i = blockIdx.x * 256 + threadIdx.x;
    if (i < NN) {
        int r = g_rowptr[i] + g_blksum[blockIdx.x];
        g_rowptr[i] = r;
        g_cursor[i] = r;
        int d = g_deg[i];
        g_dinv[i] = 1.0f / (float)(d > 1 ? d : 1);
    }
}

__global__ void k_fill(const int* __restrict__ src, const int* __restrict__ dst) {
    int e = blockIdx.x * blockDim.x + threadIdx.x;
    if (e < NE) {
        int pos = atomicAdd(&g_cursor[dst[e]], 1);
        g_col[pos] = src[e];
    }
}

// ---------------------------------------------------------------------------
// y = x @ W  (K x 48). 4 threads per node, 12 outputs per thread.
// ---------------------------------------------------------------------------
template <int K>
__global__ void k_gemm(const float* __restrict__ xin,
                       const float* __restrict__ W,
                       float* __restrict__ yout) {
    __shared__ float sW[K * H];
    for (int i = threadIdx.x; i < K * H; i += 256) sW[i] = W[i];
    __syncthreads();

    int g = (blockIdx.x * blockDim.x + threadIdx.x) >> 2;
    int t = threadIdx.x & 3;
    bool valid = g < NN;
    int n = valid ? g : NN - 1;

    float acc[12];
#pragma unroll
    for (int j = 0; j < 12; j++) acc[j] = 0.0f;

    const float4* xr = reinterpret_cast<const float4*>(xin + (size_t)n * K);
#pragma unroll 2
    for (int k0 = 0; k0 < K / 4; k0++) {
        float4 xv = xr[k0];
        float xs[4] = {xv.x, xv.y, xv.z, xv.w};
#pragma unroll
        for (int kk = 0; kk < 4; kk++) {
            const float* wr = &sW[(k0 * 4 + kk) * H + t * 12];
#pragma unroll
            for (int j = 0; j < 12; j++) acc[j] += xs[kk] * wr[j];
        }
    }

    if (valid) {
        float4* yo = reinterpret_cast<float4*>(yout + (size_t)n * H) + t * 3;
        yo[0] = make_float4(acc[0], acc[1], acc[2],  acc[3]);
        yo[1] = make_float4(acc[4], acc[5], acc[6],  acc[7]);
        yo[2] = make_float4(acc[8], acc[9], acc[10], acc[11]);
    }
}

// ---------------------------------------------------------------------------
// Fused layer:
//   agg  = sum_{s in N(n)} y_in[s]           (CSR gather)
//   h    = relu(x @ Wself + b + agg*dinv)    (stored to hout unless PRED)
//   PRED=false: y_out = h @ Wnext            (h exchanged via warp shuffles)
//   PRED=true : out[n] = h . wpred + bpred
// 4 threads per node (consecutive lanes), 12 features per thread.
// ---------------------------------------------------------------------------
template <int KSELF, bool PRED>
__global__ void k_layer(const float* __restrict__ xin,
                        const float* __restrict__ yin,
                        const float* __restrict__ Ws,
                        const float* __restrict__ bias,
                        const float* __restrict__ Wn,   // [H*H] or [H] if PRED
                        const float* __restrict__ bn,   // b_pred if PRED
                        float* __restrict__ hout,       // null if PRED
                        float* __restrict__ yout) {     // y_next or pred out
    __shared__ float sWs[KSELF * H];
    __shared__ float sWn[PRED ? H : H * H];
    __shared__ float sb[H];
    for (int i = threadIdx.x; i < KSELF * H; i += 256) sWs[i] = Ws[i];
    for (int i = threadIdx.x; i < (PRED ? H : H * H); i += 256) sWn[i] = Wn[i];
    if (threadIdx.x < H) sb[threadIdx.x] = bias[threadIdx.x];
    __syncthreads();

    int g = (blockIdx.x * blockDim.x + threadIdx.x) >> 2;
    int t = threadIdx.x & 3;
    bool valid = g < NN;
    int n = valid ? g : NN - 1;

    float acc[12];
#pragma unroll
    for (int j = 0; j < 12; j++) acc[j] = 0.0f;

    // ---- gather-aggregate over in-neighbors ----
    int start = g_rowptr[n];
    int end   = start + g_deg[n];
    int e = start;
    for (; e + 2 <= end; e += 2) {
        int s0 = g_col[e];
        int s1 = g_col[e + 1];
        const float4* r0 = reinterpret_cast<const float4*>(yin + (size_t)s0 * H) + t * 3;
        const float4* r1 = reinterpret_cast<const float4*>(yin + (size_t)s1 * H) + t * 3;
        float4 v00 = r0[0], v01 = r0[1], v02 = r0[2];
        float4 v10 = r1[0], v11 = r1[1], v12 = r1[2];
        acc[0] += v00.x; acc[1] += v00.y; acc[2]  += v00.z; acc[3]  += v00.w;
        acc[4] += v01.x; acc[5] += v01.y; acc[6]  += v01.z; acc[7]  += v01.w;
        acc[8] += v02.x; acc[9] += v02.y; acc[10] += v02.z; acc[11] += v02.w;
        acc[0] += v10.x; acc[1] += v10.y; acc[2]  += v10.z; acc[3]  += v10.w;
        acc[4] += v11.x; acc[5] += v11.y; acc[6]  += v11.z; acc[7]  += v11.w;
        acc[8] += v12.x; acc[9] += v12.y; acc[10] += v12.z; acc[11] += v12.w;
    }
    if (e < end) {
        int s0 = g_col[e];
        const float4* r0 = reinterpret_cast<const float4*>(yin + (size_t)s0 * H) + t * 3;
        float4 v00 = r0[0], v01 = r0[1], v02 = r0[2];
        acc[0] += v00.x; acc[1] += v00.y; acc[2]  += v00.z; acc[3]  += v00.w;
        acc[4] += v01.x; acc[5] += v01.y; acc[6]  += v01.z; acc[7]  += v01.w;
        acc[8] += v02.x; acc[9] += v02.y; acc[10] += v02.z; acc[11] += v02.w;
    }

    // ---- scale by 1/deg, add bias ----
    float di = g_dinv[n];
#pragma unroll
    for (int j = 0; j < 12; j++) acc[j] = acc[j] * di + sb[t * 12 + j];

    // ---- self transform: acc += x[n] @ Wself ----
    const float4* xr = reinterpret_cast<const float4*>(xin + (size_t)n * KSELF);
#pragma unroll 2
    for (int k0 = 0; k0 < KSELF / 4; k0++) {
        float4 xv = xr[k0];
        float xs[4] = {xv.x, xv.y, xv.z, xv.w};
#pragma unroll
        for (int kk = 0; kk < 4; kk++) {
            const float* wr = &sWs[(k0 * 4 + kk) * H + t * 12];
#pragma unroll
            for (int j = 0; j < 12; j++) acc[j] += xs[kk] * wr[j];
        }
    }

    // ---- ReLU ----
#pragma unroll
    for (int j = 0; j < 12; j++) acc[j] = fmaxf(acc[j], 0.0f);

    if constexpr (!PRED) {
        if (valid) {
            float4* ho = reinterpret_cast<float4*>(hout + (size_t)n * H) + t * 3;
            ho[0] = make_float4(acc[0], acc[1], acc[2],  acc[3]);
            ho[1] = make_float4(acc[4], acc[5], acc[6],  acc[7]);
            ho[2] = make_float4(acc[8], acc[9], acc[10], acc[11]);
        }
        // ---- next layer neighbor transform: y_out = h @ Wnext ----
        // full h row lives across the 4 lanes of this node; exchange via shfl
        float nacc[12];
#pragma unroll
        for (int j = 0; j < 12; j++) nacc[j] = 0.0f;
        int baseLane = (threadIdx.x & 31) & ~3;
#pragma unroll 1
        for (int ks = 0; ks < 4; ks++) {
#pragma unroll
            for (int j2 = 0; j2 < 12; j2++) {
                float hk = __shfl_sync(0xffffffffu, acc[j2], baseLane + ks);
                int k = ks * 12 + j2;
                const float* wr = &sWn[k * H + t * 12];
#pragma unroll
                for (int j = 0; j < 12; j++) nacc[j] += hk * wr[j];
            }
        }
        if (valid) {
            float4* yo = reinterpret_cast<float4*>(yout + (size_t)n * H) + t * 3;
            yo[0] = make_float4(nacc[0], nacc[1], nacc[2],  nacc[3]);
            yo[1] = make_float4(nacc[4], nacc[5], nacc[6],  nacc[7]);
            yo[2] = make_float4(nacc[8], nacc[9], nacc[10], nacc[11]);
        }
    } else {
        // ---- prediction head: out[n] = h . wpred + bpred ----
        float p = 0.0f;
#pragma unroll
        for (int j = 0; j < 12; j++) p += acc[j] * sWn[t * 12 + j];
        p += __shfl_down_sync(0xffffffffu, p, 1);
        p += __shfl_down_sync(0xffffffffu, p, 2);
        if (t == 0 && valid) yout[n] = p + bn[0];
    }
}

// ---------------------------------------------------------------------------
extern "C" void kernel_launch(void* const* d_in, const int* in_sizes, int n_in,
                              void* d_out, int out_size) {
    const float* x        = (const float*)d_in[0];
    const int*   edge     = (const int*)d_in[1];
    const float* w_self0  = (const float*)d_in[2];
    const float* w_neigh0 = (const float*)d_in[3];
    const float* b0       = (const float*)d_in[4];
    const float* w_self1  = (const float*)d_in[5];
    const float* w_neigh1 = (const float*)d_in[6];
    const float* b1       = (const float*)d_in[7];
    const float* w_self2  = (const float*)d_in[8];
    const float* w_neigh2 = (const float*)d_in[9];
    const float* b2       = (const float*)d_in[10];
    const float* w_pred   = (const float*)d_in[11];
    const float* b_pred   = (const float*)d_in[12];
    float* out = (float*)d_out;

    const int* src = edge;
    const int* dst = edge + NE;

    float *y0, *y1, *h0, *h1;
    cudaGetSymbolAddress((void**)&y0, g_y0);
    cudaGetSymbolAddress((void**)&y1, g_y1);
    cudaGetSymbolAddress((void**)&h0, g_h0);
    cudaGetSymbolAddress((void**)&h1, g_h1);

    const int gE = NE / 256;                    // 3125
    const int gN = (NN * 4 + 255) / 256;        // 782 (4 threads/node)

    // CSR build
    k_zero_deg<<<SCAN_BLOCKS, 256>>>();
    k_count_deg<<<gE, 256>>>(dst);
    k_scan1<<<SCAN_BLOCKS, 256>>>();
    k_scan2<<<1, 256>>>();
    k_scan3<<<SCAN_BLOCKS, 256>>>();
    k_fill<<<gE, 256>>>(src, dst);

    // y0 = x @ w_neigh0
    k_gemm<F0><<<gN, 256>>>(x, w_neigh0, y0);

    // Layer 0: h0 = relu(x@Ws0 + b0 + agg(y0)*dinv); y1 = h0 @ w_neigh1
    k_layer<F0, false><<<gN, 256>>>(x,  y0, w_self0, b0, w_neigh1, nullptr, h0, y1);
    // Layer 1: h1 = relu(h0@Ws1 + b1 + agg(y1)*dinv); y0 = h1 @ w_neigh2
    k_layer<H,  false><<<gN, 256>>>(h0, y1, w_self1, b1, w_neigh2, nullptr, h1, y0);
    // Layer 2 + head: out = relu(h1@Ws2 + b2 + agg(y0)*dinv) . w_pred + b_pred
    k_layer<H,  true ><<<gN, 256>>>(h1, y0, w_self2, b2, w_pred,  b_pred, nullptr, out);
}

// round 3
// speedup vs baseline: 1.6477x; 1.1247x over previous
#include <cuda_runtime.h>
#include <cuda_fp16.h>

// GraphSAGENet: 50000 nodes, 800000 edges, feats 96 -> 48 -> 48 -> 48 -> 1
constexpr int NN = 50000;
constexpr int NE = 800000;
constexpr int F0 = 96;
constexpr int H  = 48;
constexpr int GFILL = NE / 256;            // 3125 (NE divisible by 256)
constexpr int GNODE = (NN * 4 + 255) / 256; // 782 (4 threads per node)

// Scratch (static device globals; zero-initialized at module load).
// g_deg and g_alloc are re-zeroed at the tail of the last kernel each call,
// so every execution of kernel_launch sees them zeroed.
__device__ uint4 g_y0[NN * 6];   // fp16 y rows: 48 halfs = 96 B = 6 uint4
__device__ uint4 g_y1[NN * 6];
__device__ float g_h0[NN * H];
__device__ float g_h1[NN * H];
__device__ int   g_deg[NN];
__device__ int   g_alloc;
__device__ int2  g_seg[NN];      // (start, deg)
__device__ float g_dinv[NN];
__device__ int   g_cursor[NN];
__device__ int   g_col[NE];

// fp16 pack/unpack helpers
__device__ __forceinline__ unsigned pack2(float a, float b) {
    __half2 h = __float22half2_rn(make_float2(a, b));
    return *reinterpret_cast<unsigned*>(&h);
}
__device__ __forceinline__ float2 up2(unsigned u) {
    __half2 h = *reinterpret_cast<__half2*>(&u);
    return __half22float2(h);
}

// Accumulate one fp16 row chunk (uint4 = slots 0..7, uint2 = slots 8..11)
__device__ __forceinline__ void acc_row(float* acc, uint4 a, uint2 b) {
    float2 f;
    f = up2(a.x); acc[0] += f.x; acc[1]  += f.y;
    f = up2(a.y); acc[2] += f.x; acc[3]  += f.y;
    f = up2(a.z); acc[4] += f.x; acc[5]  += f.y;
    f = up2(a.w); acc[6] += f.x; acc[7]  += f.y;
    f = up2(b.x); acc[8] += f.x; acc[9]  += f.y;
    f = up2(b.y); acc[10] += f.x; acc[11] += f.y;
}

// Feature mapping: lane t owns feats [8t..8t+7] (slots 0..7)
//                  and feats [32+4t..32+4t+3] (slots 8..11)

// ---------------------------------------------------------------------------
// degree histogram (g_deg must be zero on entry; tail of k_layer<PRED> zeroes it)
// ---------------------------------------------------------------------------
__global__ void k_count(const int* __restrict__ dst) {
    int e = blockIdx.x * 256 + threadIdx.x;
    atomicAdd(&g_deg[dst[e]], 1);
}

// ---------------------------------------------------------------------------
// segment allocation: start = atomicAdd(g_alloc, deg), warp-aggregated.
// Segment order is arbitrary — gather only needs per-node contiguity.
// ---------------------------------------------------------------------------
__global__ void k_alloc() {
    int i = blockIdx.x * 256 + threadIdx.x;
    int lane = threadIdx.x & 31;
    int d = (i < NN) ? g_deg[i] : 0;

    // inclusive warp scan of d
    int s = d;
#pragma unroll
    for (int off = 1; off < 32; off <<= 1) {
        int t = __shfl_up_sync(0xffffffffu, s, off);
        if (lane >= off) s += t;
    }
    int total = __shfl_sync(0xffffffffu, s, 31);
    int base = 0;
    if (lane == 31) base = atomicAdd(&g_alloc, total);
    base = __shfl_sync(0xffffffffu, base, 31);
    int start = base + s - d;

    if (i < NN) {
        g_seg[i] = make_int2(start, d);
        g_cursor[i] = start;
        g_dinv[i] = 1.0f / (float)(d > 1 ? d : 1);
    }
}

// ---------------------------------------------------------------------------
// Fused: blocks [0,GFILL) fill the CSR column array;
//        blocks [GFILL,GFILL+GNODE) compute y0 = x @ W_neigh0 (fp16 out).
// These are independent, so they overlap inside one launch.
// ---------------------------------------------------------------------------
__global__ void k_fill_gemm(const int* __restrict__ src,
                            const int* __restrict__ dst,
                            const float* __restrict__ x,
                            const float* __restrict__ W,
                            uint4* __restrict__ yout) {
    __shared__ float sW[F0 * H];

    if (blockIdx.x < GFILL) {
        int e = blockIdx.x * 256 + threadIdx.x;
        int pos = atomicAdd(&g_cursor[dst[e]], 1);
        g_col[pos] = src[e];
        return;
    }

    for (int i = threadIdx.x; i < F0 * H; i += 256) sW[i] = W[i];
    __syncthreads();

    int idx = (blockIdx.x - GFILL) * 256 + threadIdx.x;
    int g = idx >> 2;
    int t = idx & 3;
    if (g >= NN) return;

    float acc[12];
#pragma unroll
    for (int j = 0; j < 12; j++) acc[j] = 0.0f;

    const float4* xr = reinterpret_cast<const float4*>(x + (size_t)g * F0);
#pragma unroll 2
    for (int k0 = 0; k0 < F0 / 4; k0++) {
        float4 xv = xr[k0];
        float xs[4] = {xv.x, xv.y, xv.z, xv.w};
#pragma unroll
        for (int kk = 0; kk < 4; kk++) {
            const float* wr = &sW[(k0 * 4 + kk) * H];
#pragma unroll
            for (int j = 0; j < 8; j++) acc[j] += xs[kk] * wr[t * 8 + j];
#pragma unroll
            for (int j = 0; j < 4; j++) acc[8 + j] += xs[kk] * wr[32 + t * 4 + j];
        }
    }

    uint4* row = yout + (size_t)g * 6;
    uint4 o;
    o.x = pack2(acc[0], acc[1]); o.y = pack2(acc[2], acc[3]);
    o.z = pack2(acc[4], acc[5]); o.w = pack2(acc[6], acc[7]);
    row[t] = o;
    uint2* row2 = reinterpret_cast<uint2*>(row + 4);
    row2[t] = make_uint2(pack2(acc[8], acc[9]), pack2(acc[10], acc[11]));
}

// ---------------------------------------------------------------------------
// Fused layer:
//   agg = sum_{s in N(n)} y_in[s]  (fp16 gather, fp32 accumulate)
//   h   = relu(x @ Wself + b + agg*dinv)
//   !PRED: store h; y_out = h @ Wnext (h exchanged across 4 lanes via shfl)
//   PRED : out[n] = h . wpred + bpred; tail: zero g_deg / g_alloc for next call
// ---------------------------------------------------------------------------
template <int KSELF, bool PRED>
__global__ void k_layer(const float* __restrict__ xin,
                        const uint4* __restrict__ yin,
                        const float* __restrict__ Ws,
                        const float* __restrict__ bias,
                        const float* __restrict__ Wn,   // [H*H] or [H] if PRED
                        const float* __restrict__ bn,   // b_pred if PRED
                        float* __restrict__ hout,       // null if PRED
                        void* __restrict__ yout_) {     // uint4* y_next or float* out
    __shared__ float sWs[KSELF * H];
    __shared__ float sWn[PRED ? H : H * H];
    __shared__ float sb[H];
    for (int i = threadIdx.x; i < KSELF * H; i += 256) sWs[i] = Ws[i];
    for (int i = threadIdx.x; i < (PRED ? H : H * H); i += 256) sWn[i] = Wn[i];
    if (threadIdx.x < H) sb[threadIdx.x] = bias[threadIdx.x];
    __syncthreads();

    int gid = blockIdx.x * 256 + threadIdx.x;
    int g = gid >> 2;
    int t = gid & 3;
    bool valid = g < NN;
    int n = valid ? g : NN - 1;

    float acc[12];
#pragma unroll
    for (int j = 0; j < 12; j++) acc[j] = 0.0f;

    // ---- gather-aggregate over in-neighbors (fp16 rows) ----
    int2 seg = g_seg[n];
    int e = seg.x, end = seg.x + seg.y;
    for (; e + 2 <= end; e += 2) {
        int s0 = g_col[e];
        int s1 = g_col[e + 1];
        const uint4* r0 = yin + (size_t)s0 * 6;
        const uint4* r1 = yin + (size_t)s1 * 6;
        uint4 a0 = r0[t];
        uint2 b0 = reinterpret_cast<const uint2*>(r0 + 4)[t];
        uint4 a1 = r1[t];
        uint2 b1 = reinterpret_cast<const uint2*>(r1 + 4)[t];
        acc_row(acc, a0, b0);
        acc_row(acc, a1, b1);
    }
    if (e < end) {
        int s0 = g_col[e];
        const uint4* r0 = yin + (size_t)s0 * 6;
        uint4 a0 = r0[t];
        uint2 b0 = reinterpret_cast<const uint2*>(r0 + 4)[t];
        acc_row(acc, a0, b0);
    }

    // ---- scale by 1/deg, add bias ----
    float di = g_dinv[n];
#pragma unroll
    for (int j = 0; j < 8; j++)  acc[j] = acc[j] * di + sb[t * 8 + j];
#pragma unroll
    for (int j = 0; j < 4; j++)  acc[8 + j] = acc[8 + j] * di + sb[32 + t * 4 + j];

    // ---- self transform: acc += x[n] @ Wself ----
    const float4* xr = reinterpret_cast<const float4*>(xin + (size_t)n * KSELF);
#pragma unroll 2
    for (int k0 = 0; k0 < KSELF / 4; k0++) {
        float4 xv = xr[k0];
        float xs[4] = {xv.x, xv.y, xv.z, xv.w};
#pragma unroll
        for (int kk = 0; kk < 4; kk++) {
            const float* wr = &sWs[(k0 * 4 + kk) * H];
#pragma unroll
            for (int j = 0; j < 8; j++) acc[j] += xs[kk] * wr[t * 8 + j];
#pragma unroll
            for (int j = 0; j < 4; j++) acc[8 + j] += xs[kk] * wr[32 + t * 4 + j];
        }
    }

    // ---- ReLU ----
#pragma unroll
    for (int j = 0; j < 12; j++) acc[j] = fmaxf(acc[j], 0.0f);

    if constexpr (!PRED) {
        // store h (natural feature order, all vectors aligned)
        if (valid) {
            float* hr = hout + (size_t)n * H;
            float4* h4 = reinterpret_cast<float4*>(hr);
            h4[2 * t]     = make_float4(acc[0], acc[1], acc[2], acc[3]);
            h4[2 * t + 1] = make_float4(acc[4], acc[5], acc[6], acc[7]);
            reinterpret_cast<float4*>(hr + 32)[t] =
                make_float4(acc[8], acc[9], acc[10], acc[11]);
        }
        // next layer neighbor transform: y_out = h @ Wnext (fp16 out)
        float nacc[12];
#pragma unroll
        for (int j = 0; j < 12; j++) nacc[j] = 0.0f;
        int baseLane = (threadIdx.x & 31) & ~3;
#pragma unroll 1
        for (int q = 0; q < 4; q++) {
#pragma unroll
            for (int m = 0; m < 12; m++) {
                float hk = __shfl_sync(0xffffffffu, acc[m], baseLane + q);
                int k = (m < 8) ? (q * 8 + m) : (32 + q * 4 + (m - 8));
                const float* wr = &sWn[k * H];
#pragma unroll
                for (int j = 0; j < 8; j++) nacc[j] += hk * wr[t * 8 + j];
#pragma unroll
                for (int j = 0; j < 4; j++) nacc[8 + j] += hk * wr[32 + t * 4 + j];
            }
        }
        if (valid) {
            uint4* row = reinterpret_cast<uint4*>(yout_) + (size_t)n * 6;
            uint4 o;
            o.x = pack2(nacc[0], nacc[1]); o.y = pack2(nacc[2], nacc[3]);
            o.z = pack2(nacc[4], nacc[5]); o.w = pack2(nacc[6], nacc[7]);
            row[t] = o;
            reinterpret_cast<uint2*>(row + 4)[t] =
                make_uint2(pack2(nacc[8], nacc[9]), pack2(nacc[10], nacc[11]));
        }
    } else {
        // prediction head
        float p = 0.0f;
#pragma unroll
        for (int j = 0; j < 8; j++) p += acc[j] * sWn[t * 8 + j];
#pragma unroll
        for (int j = 0; j < 4; j++) p += acc[8 + j] * sWn[32 + t * 4 + j];
        p += __shfl_down_sync(0xffffffffu, p, 1);
        p += __shfl_down_sync(0xffffffffu, p, 2);
        if (t == 0 && valid) reinterpret_cast<float*>(yout_)[n] = p + bn[0];

        // tail cleanup: restore zeroed state for the next call (no reads of
        // g_deg / g_alloc happen in this kernel, so no race)
        if (gid < NN) g_deg[gid] = 0;
        if (gid == 0) g_alloc = 0;
    }
}

// ---------------------------------------------------------------------------
extern "C" void kernel_launch(void* const* d_in, const int* in_sizes, int n_in,
                              void* d_out, int out_size) {
    const float* x        = (const float*)d_in[0];
    const int*   edge     = (const int*)d_in[1];
    const float* w_self0  = (const float*)d_in[2];
    const float* w_neigh0 = (const float*)d_in[3];
    const float* b0       = (const float*)d_in[4];
    const float* w_self1  = (const float*)d_in[5];
    const float* w_neigh1 = (const float*)d_in[6];
    const float* b1       = (const float*)d_in[7];
    const float* w_self2  = (const float*)d_in[8];
    const float* w_neigh2 = (const float*)d_in[9];
    const float* b2       = (const float*)d_in[10];
    const float* w_pred   = (const float*)d_in[11];
    const float* b_pred   = (const float*)d_in[12];
    float* out = (float*)d_out;

    const int* src = edge;
    const int* dst = edge + NE;

    uint4 *y0, *y1;
    float *h0, *h1;
    cudaGetSymbolAddress((void**)&y0, g_y0);
    cudaGetSymbolAddress((void**)&y1, g_y1);
    cudaGetSymbolAddress((void**)&h0, g_h0);
    cudaGetSymbolAddress((void**)&h1, g_h1);

    // CSR build (no scan: arbitrary-order segment allocation)
    k_count<<<GFILL, 256>>>(dst);
    k_alloc<<<(NN + 255) / 256, 256>>>();
    // CSR fill fused with y0 = x @ w_neigh0 (independent work, one launch)
    k_fill_gemm<<<GFILL + GNODE, 256>>>(src, dst, x, w_neigh0, y0);

    // Layer 0: h0 = relu(x@Ws0 + b0 + agg(y0)*dinv); y1 = h0 @ w_neigh1
    k_layer<F0, false><<<GNODE, 256>>>(x,  y0, w_self0, b0, w_neigh1, nullptr, h0, y1);
    // Layer 1: h1 = relu(h0@Ws1 + b1 + agg(y1)*dinv); y0 = h1 @ w_neigh2
    k_layer<H,  false><<<GNODE, 256>>>(h0, y1, w_self1, b1, w_neigh2, nullptr, h1, y0);
    // Layer 2 + head (+ state reset for next call)
    k_layer<H,  true ><<<GNODE, 256>>>(h1, y0, w_self2, b2, w_pred,  b_pred, nullptr, out);
}